// round 7
// baseline (speedup 1.0000x reference)
#include <cuda_runtime.h>
#include <math.h>

#define D      2048
#define RNK    32
#define NST    16
#define LAYER  11
#define GRID   148
#define NTHR   512
#define NWARP  16

// Scratch (device globals; persist across graph replays)
__device__ float g_z1[3][D];
__device__ float g_u[2][3][D];               // [0]=f (fconv), [1]=bw (bconv)
__device__ float g_dbc[2][3][64];
__device__ unsigned long long g_bar;          // monotonic grid-barrier counter

__device__ __forceinline__ float warp_sum(float v) {     // result in lane 0
    v += __shfl_down_sync(0xffffffffu, v, 16);
    v += __shfl_down_sync(0xffffffffu, v, 8);
    v += __shfl_down_sync(0xffffffffu, v, 4);
    v += __shfl_down_sync(0xffffffffu, v, 2);
    v += __shfl_down_sync(0xffffffffu, v, 1);
    return v;
}
__device__ __forceinline__ float warp_sum_all(float v) {  // result in ALL lanes
    v += __shfl_xor_sync(0xffffffffu, v, 16);
    v += __shfl_xor_sync(0xffffffffu, v, 8);
    v += __shfl_xor_sync(0xffffffffu, v, 4);
    v += __shfl_xor_sync(0xffffffffu, v, 2);
    v += __shfl_xor_sync(0xffffffffu, v, 1);
    return v;
}

// Grid barrier: monotonic counter, round-up target. Replay-safe (never resets).
// GRID=148 blocks of 512 thr -> exactly 1 per SM, all co-resident.
__device__ __forceinline__ void grid_bar() {
    __syncthreads();
    if (threadIdx.x == 0) {
        __threadfence();
        unsigned long long my = atomicAdd(&g_bar, 1ull) + 1ull;
        unsigned long long target = ((my + (GRID - 1ull)) / GRID) * GRID;
        volatile unsigned long long* p = (volatile unsigned long long*)&g_bar;
        while (*p < target) { }
        __threadfence();
    }
    __syncthreads();
}

__device__ __forceinline__ float softplus_f(float v) {
    return fmaxf(v, 0.f) + log1pf(expf(-fabsf(v)));
}

// Full-K row dot of W[row] against 3 smem vectors, 8-deep load batching.
// Returns (a0,a1,a2) reduced to lane 0.
__device__ __forceinline__ void row_dot(
        const float* __restrict__ W, int row,
        const float4* __restrict__ x0, const float4* __restrict__ x1,
        const float4* __restrict__ x2, int l,
        float& r0, float& r1, float& r2) {
    const float4* wrow = (const float4*)(W + (size_t)row * D);
    float a0 = 0.f, a1 = 0.f, a2 = 0.f;
    #pragma unroll
    for (int half = 0; half < 2; half++) {
        float4 wreg[8];
        #pragma unroll
        for (int j = 0; j < 8; j++)
            wreg[j] = wrow[half * 256 + j * 32 + l];    // 8 LDG.128 in flight
        #pragma unroll
        for (int j = 0; j < 8; j++) {
            const int idx = half * 256 + j * 32 + l;
            float4 v0 = x0[idx], v1 = x1[idx], v2 = x2[idx];
            a0 += wreg[j].x*v0.x + wreg[j].y*v0.y + wreg[j].z*v0.z + wreg[j].w*v0.w;
            a1 += wreg[j].x*v1.x + wreg[j].y*v1.y + wreg[j].z*v1.z + wreg[j].w*v1.w;
            a2 += wreg[j].x*v2.x + wreg[j].y*v2.y + wreg[j].z*v2.z + wreg[j].w*v2.w;
        }
    }
    r0 = warp_sum(a0); r1 = warp_sum(a1); r2 = warp_sum(a2);
}

// ---------------------------------------------------------------------------
__global__ void __launch_bounds__(NTHR, 1) k_all(
        const float* __restrict__ x,
        const float* __restrict__ gam,
        const float* __restrict__ bet,
        const float* __restrict__ Wp,  const float* __restrict__ bp,
        const float* __restrict__ Wf,  const float* __restrict__ bf,
        const float* __restrict__ Wb,  const float* __restrict__ bb_,
        const float* __restrict__ Wdbc,
        const float* __restrict__ dtp_w,
        const float* __restrict__ dtp_b,
        const float* __restrict__ Dp,
        float* __restrict__ out) {
    __shared__ float s_in[3][D];          // 24 KB (xn, then z1)
    __shared__ float red[NWARP][6];
    __shared__ float mu_s[3], inv_s[3];
    __shared__ float s_dbc[2][3][64];
    __shared__ float s_bc[2][3];

    const int tid = threadIdx.x;
    const int w   = tid >> 5;
    const int l   = tid & 31;
    const int blk = blockIdx.x;

    const float4* x0 = (const float4*)s_in[0];
    const float4* x1 = (const float4*)s_in[1];
    const float4* x2 = (const float4*)s_in[2];

    // ===================== Phase A: layernorm + proj ========================
    {
        // stage x: 512 float4 per vector, 1 per thread per vector
        float sm[3], sq[3];
        #pragma unroll
        for (int b = 0; b < 3; b++) {
            float4 v = ((const float4*)(x + b * D))[tid];
            ((float4*)s_in[b])[tid] = v;
            sm[b] = v.x + v.y + v.z + v.w;
            sq[b] = v.x*v.x + v.y*v.y + v.z*v.z + v.w*v.w;
        }
        #pragma unroll
        for (int b = 0; b < 3; b++) { sm[b] = warp_sum(sm[b]); sq[b] = warp_sum(sq[b]); }
        if (l == 0) {
            #pragma unroll
            for (int b = 0; b < 3; b++) { red[w][b] = sm[b]; red[w][3 + b] = sq[b]; }
        }
        __syncthreads();
        if (tid < 3) {
            float S = 0.f, Q = 0.f;
            #pragma unroll
            for (int i = 0; i < NWARP; i++) { S += red[i][tid]; Q += red[i][3 + tid]; }
            float mu = S * (1.f / D);
            float var = Q * (1.f / D) - mu * mu;
            mu_s[tid] = mu;
            inv_s[tid] = rsqrtf(var + 1e-5f);
        }
        __syncthreads();
        {
            const float4 g4 = ((const float4*)gam)[tid];
            const float4 b4 = ((const float4*)bet)[tid];
            #pragma unroll
            for (int b = 0; b < 3; b++) {
                const float mu = mu_s[b], inv = inv_s[b];
                float4 v = ((float4*)s_in[b])[tid];
                v.x = (v.x - mu) * inv * g4.x + b4.x;
                v.y = (v.y - mu) * inv * g4.y + b4.y;
                v.z = (v.z - mu) * inv * g4.z + b4.z;
                v.w = (v.w - mu) * inv * g4.w + b4.w;
                ((float4*)s_in[b])[tid] = v;
            }
        }
        __syncthreads();

        // rows [rs, re) for this block; one row per warp (cnt <= 14 < 16)
        const int rs = (blk * 2048) / GRID;
        const int re = ((blk + 1) * 2048) / GRID;
        const int row = rs + w;
        if (row < re) {
            float r0, r1, r2;
            row_dot(Wp, row, x0, x1, x2, l, r0, r1, r2);
            if (l == 0) {
                const float bv = bp[row];
                g_z1[0][row] = r0 + bv;
                g_z1[1][row] = r1 + bv;
                g_z1[2][row] = r2 + bv;
            }
        }
    }
    grid_bar();

    // ===================== Phase B: f/b conv matvecs ========================
    {
        #pragma unroll
        for (int b = 0; b < 3; b++)
            ((float4*)s_in[b])[tid] = ((const float4*)&g_z1[b][0])[tid];
        __syncthreads();

        // virtual rows [0,4096): 0..2047 -> Wf, 2048..4095 -> Wb
        const int rs = (blk * 4096) / GRID;
        const int re = ((blk + 1) * 4096) / GRID;
        for (int r = rs + w; r < re; r += NWARP) {      // <= 2 rows per warp
            const int which = r >> 11;
            const int rowi  = r & 2047;
            const float* W = which ? Wb : Wf;
            float r0, r1, r2;
            row_dot(W, rowi, x0, x1, x2, l, r0, r1, r2);
            if (l == 0) {
                const float bv = which ? bb_[rowi] : bf[rowi];
                g_u[which][0][rowi] = r0 + bv;
                g_u[which][1][rowi] = r1 + bv;
                g_u[which][2][rowi] = r2 + bv;
            }
        }
    }
    grid_bar();

    // ===================== Phase C: dbc = dbc_w @ u (64 rows) ===============
    if (blk < 64) {
        const int e = blk;
        const float4* w4 = (const float4*)(Wdbc + (size_t)e * D);
        const float4* u4 = (const float4*)&g_u[0][0][0];   // 6 vecs x 512 float4

        float4 wv = w4[tid];                 // exactly 512 float4, 1 per thread
        float acc[6];
        #pragma unroll
        for (int v = 0; v < 6; v++) {
            float4 uv = u4[v * 512 + tid];
            acc[v] = wv.x*uv.x + wv.y*uv.y + wv.z*uv.z + wv.w*uv.w;
        }
        #pragma unroll
        for (int v = 0; v < 6; v++) acc[v] = warp_sum(acc[v]);
        if (l == 0) {
            #pragma unroll
            for (int v = 0; v < 6; v++) red[w][v] = acc[v];
        }
        __syncthreads();
        if (tid < 6) {
            float s = 0.f;
            #pragma unroll
            for (int i = 0; i < NWARP; i++) s += red[i][tid];
            (&g_dbc[0][0][0])[tid * 64 + e] = s;
        }
    }
    grid_bar();

    // ===================== Phase D: delta / gate / residual =================
    {
        if (tid < 2 * 3 * 64)
            (&s_dbc[0][0][0])[tid] = (&g_dbc[0][0][0])[tid];
        __syncthreads();
        if (tid < 6) {
            const int ww = tid / 3, b = tid % 3;
            float s = 0.f;
            #pragma unroll
            for (int n = 0; n < NST; n++)
                s += s_dbc[ww][b][RNK + n] * s_dbc[ww][b][RNK + NST + n];
            s_bc[ww][b] = s;
        }
        __syncthreads();

        // warp-per-d: global warp id < 2048
        const int gw = blk * NWARP + w;
        if (gw < 2048) {
            const int d = gw;
            const float wr = dtp_w[(size_t)d * RNK + l];
            float s_f[3], s_b[3];
            #pragma unroll
            for (int b = 0; b < 3; b++) {
                s_f[b] = warp_sum_all(wr * s_dbc[0][b][l]);
                s_b[b] = warp_sum_all(wr * s_dbc[1][b][l]);
            }
            if (l < 3) {
                const int b = l;
                const float tb = dtp_b[d];
                const float dpv = Dp[d];
                const float df = softplus_f(s_f[b] + tb);
                const float db = softplus_f(s_b[b] + tb);
                const float y = g_u[0][b][d] * (df * s_bc[0][b] + dpv)
                              + g_u[1][b][d] * (db * s_bc[1][b] + dpv);
                const float z = g_z1[b][d];
                const float si = z / (1.f + expf(-z));
                out[b * D + d] = y * si + x[b * D + d];
            }
        }
    }
}

// ---------------------------------------------------------------------------
extern "C" void kernel_launch(void* const* d_in, const int* in_sizes, int n_in,
                              void* d_out, int out_size) {
    const float* x    = (const float*)d_in[0];
    const float* ng   = (const float*)d_in[1]  + (size_t)LAYER * D;
    const float* nb   = (const float*)d_in[2]  + (size_t)LAYER * D;
    const float* pw   = (const float*)d_in[3]  + (size_t)LAYER * D * D;
    const float* pb   = (const float*)d_in[4]  + (size_t)LAYER * D;
    const float* fw   = (const float*)d_in[5]  + (size_t)LAYER * D * D;
    const float* fb   = (const float*)d_in[6]  + (size_t)LAYER * D;
    const float* bw   = (const float*)d_in[7]  + (size_t)LAYER * D * D;
    const float* bb   = (const float*)d_in[8]  + (size_t)LAYER * D;
    const float* dbcw = (const float*)d_in[9]  + (size_t)LAYER * (RNK + 2 * NST) * D;
    const float* dtpw = (const float*)d_in[10] + (size_t)LAYER * D * RNK;
    const float* dtpb = (const float*)d_in[11] + (size_t)LAYER * D;
    // d_in[12] = A_log : unused (seq len 1, h0 = 0 -> dA*h term vanishes)
    const float* Dp   = (const float*)d_in[13] + (size_t)LAYER * D;
    float* out = (float*)d_out;

    k_all<<<GRID, NTHR>>>(x, ng, nb, pw, pb, fw, fb, bw, bb,
                          dbcw, dtpw, dtpb, Dp, out);
}

// round 8
// speedup vs baseline: 1.1648x; 1.1648x over previous
#include <cuda_runtime.h>
#include <math.h>

#define D      2048
#define RNK    32
#define NST    16
#define LAYER  11
#define GRID   148
#define NTHR   1024
#define NWARP  32
#define CHA    128      // phase A chunks: 2048 rows / 16 rows-per-chunk
#define CHB    128      // phase B chunks: 4096 rows / 32 rows-per-chunk

// Scratch (device globals; persist across graph replays)
__device__ float g_z1[3][D];
__device__ float g_u[2][3][D];               // [0]=f (fconv), [1]=bw (bconv)
__device__ float g_dbc[2][3][64];
__device__ unsigned long long g_bar;          // monotonic grid-barrier counter
__device__ unsigned int g_ctrA;               // phase-A chunk counter (reset each launch)
__device__ unsigned int g_ctrB;               // phase-B chunk counter (reset each launch)

__device__ __forceinline__ float warp_sum(float v) {     // result in lane 0
    v += __shfl_down_sync(0xffffffffu, v, 16);
    v += __shfl_down_sync(0xffffffffu, v, 8);
    v += __shfl_down_sync(0xffffffffu, v, 4);
    v += __shfl_down_sync(0xffffffffu, v, 2);
    v += __shfl_down_sync(0xffffffffu, v, 1);
    return v;
}
__device__ __forceinline__ float warp_sum_all(float v) {  // result in ALL lanes
    v += __shfl_xor_sync(0xffffffffu, v, 16);
    v += __shfl_xor_sync(0xffffffffu, v, 8);
    v += __shfl_xor_sync(0xffffffffu, v, 4);
    v += __shfl_xor_sync(0xffffffffu, v, 2);
    v += __shfl_xor_sync(0xffffffffu, v, 1);
    return v;
}

// Grid barrier: monotonic counter, round-up target. Replay-safe (never resets).
// GRID=148 blocks of 1024 thr -> exactly 1 per SM, all co-resident.
__device__ __forceinline__ void grid_bar() {
    __syncthreads();
    if (threadIdx.x == 0) {
        __threadfence();
        unsigned long long my = atomicAdd(&g_bar, 1ull) + 1ull;
        unsigned long long target = ((my + (GRID - 1ull)) / GRID) * GRID;
        volatile unsigned long long* p = (volatile unsigned long long*)&g_bar;
        while (*p < target) { }
        __threadfence();
    }
    __syncthreads();
}

__device__ __forceinline__ float softplus_f(float v) {
    return fmaxf(v, 0.f) + log1pf(expf(-fabsf(v)));
}

// ---------------------------------------------------------------------------
__global__ void __launch_bounds__(NTHR, 1) k_all(
        const float* __restrict__ x,
        const float* __restrict__ gam,
        const float* __restrict__ bet,
        const float* __restrict__ Wp,  const float* __restrict__ bp,
        const float* __restrict__ Wf,  const float* __restrict__ bf,
        const float* __restrict__ Wb,  const float* __restrict__ bb_,
        const float* __restrict__ Wdbc,
        const float* __restrict__ dtp_w,
        const float* __restrict__ dtp_b,
        const float* __restrict__ Dp,
        float* __restrict__ out) {
    __shared__ float s_in[3][D];          // 24 KB (xn, then z1)
    __shared__ float s_part[NWARP][3];
    __shared__ float red[NWARP][6];
    __shared__ float mu_s[3], inv_s[3];
    __shared__ float s_dbc[2][3][64];
    __shared__ float s_bc[2][3];
    __shared__ int s_chunk;

    const int tid = threadIdx.x;
    const int w   = tid >> 5;
    const int l   = tid & 31;
    const int blk = blockIdx.x;

    const float4* x0 = (const float4*)s_in[0];
    const float4* x1 = (const float4*)s_in[1];
    const float4* x2 = (const float4*)s_in[2];

    // ===================== Phase A: layernorm + proj (stolen chunks) ========
    {
        float sm[3] = {0.f, 0.f, 0.f}, sq[3] = {0.f, 0.f, 0.f};
        #pragma unroll
        for (int rep = 0; rep < 2; rep++) {
            const int i = rep * NTHR + tid;
            #pragma unroll
            for (int b = 0; b < 3; b++) {
                float v = x[b * D + i];
                s_in[b][i] = v;
                sm[b] += v;
                sq[b] += v * v;
            }
        }
        #pragma unroll
        for (int b = 0; b < 3; b++) { sm[b] = warp_sum(sm[b]); sq[b] = warp_sum(sq[b]); }
        if (l == 0) {
            #pragma unroll
            for (int b = 0; b < 3; b++) { red[w][b] = sm[b]; red[w][3 + b] = sq[b]; }
        }
        // grab first chunk while LN reduction settles
        if (tid == 0) s_chunk = (int)atomicAdd(&g_ctrA, 1u);
        __syncthreads();
        if (tid < 3) {
            float S = 0.f, Q = 0.f;
            #pragma unroll
            for (int i = 0; i < NWARP; i++) { S += red[i][tid]; Q += red[i][3 + tid]; }
            float mu = S * (1.f / D);
            float var = Q * (1.f / D) - mu * mu;
            mu_s[tid] = mu;
            inv_s[tid] = rsqrtf(var + 1e-5f);
        }
        __syncthreads();
        const float m0 = mu_s[0], m1 = mu_s[1], m2 = mu_s[2];
        const float i0 = inv_s[0], i1 = inv_s[1], i2 = inv_s[2];
        #pragma unroll
        for (int rep = 0; rep < 2; rep++) {
            const int i = rep * NTHR + tid;
            const float g = gam[i], be = bet[i];
            s_in[0][i] = (s_in[0][i] - m0) * i0 * g + be;
            s_in[1][i] = (s_in[1][i] - m1) * i1 * g + be;
            s_in[2][i] = (s_in[2][i] - m2) * i2 * g + be;
        }
        __syncthreads();

        // chunks of 16 rows; 2 warps per row (K-halves)
        int c = s_chunk;
        while (c < CHA) {
            __syncthreads();
            if (tid == 0) s_chunk = (int)atomicAdd(&g_ctrA, 1u);  // prefetch next

            const int rw   = w >> 1;
            const int half = w & 1;
            const int row  = c * 16 + rw;
            const float4* wp4 = (const float4*)(Wp + (size_t)row * D) + half * 256;
            float a0 = 0.f, a1 = 0.f, a2 = 0.f;
            #pragma unroll
            for (int it = 0; it < 8; it++) {
                const int idx = it * 32 + l;
                float4 wv = wp4[idx];
                float4 v0 = x0[half * 256 + idx], v1 = x1[half * 256 + idx],
                       v2 = x2[half * 256 + idx];
                a0 += wv.x*v0.x + wv.y*v0.y + wv.z*v0.z + wv.w*v0.w;
                a1 += wv.x*v1.x + wv.y*v1.y + wv.z*v1.z + wv.w*v1.w;
                a2 += wv.x*v2.x + wv.y*v2.y + wv.z*v2.z + wv.w*v2.w;
            }
            a0 = warp_sum(a0); a1 = warp_sum(a1); a2 = warp_sum(a2);
            if (l == 0) { s_part[w][0] = a0; s_part[w][1] = a1; s_part[w][2] = a2; }
            __syncthreads();
            if (tid < 48) {   // 16 rows x 3 batches
                const int rr = tid / 3, b = tid % 3;
                const int row_g = c * 16 + rr;
                g_z1[b][row_g] = s_part[2 * rr][b] + s_part[2 * rr + 1][b] + bp[row_g];
            }
            c = s_chunk;
        }
    }
    grid_bar();

    // ===================== Phase B: f/b conv matvecs (stolen chunks) ========
    {
        #pragma unroll
        for (int rep = 0; rep < 6; rep++)
            (&s_in[0][0])[rep * NTHR + tid] = (&g_z1[0][0])[rep * NTHR + tid];
        if (tid == 0) s_chunk = (int)atomicAdd(&g_ctrB, 1u);
        __syncthreads();

        int c = s_chunk;
        while (c < CHB) {
            __syncthreads();
            if (tid == 0) s_chunk = (int)atomicAdd(&g_ctrB, 1u);  // prefetch next

            // virtual row: 0..2047 -> Wf, 2048..4095 -> Wb; 1 row per warp
            const int r     = c * 32 + w;
            const int which = r >> 11;
            const int rowi  = r & 2047;
            const float* W  = which ? Wb : Wf;

            const float4* w4 = (const float4*)(W + (size_t)rowi * D);
            float a0 = 0.f, a1 = 0.f, a2 = 0.f;
            #pragma unroll
            for (int it = 0; it < 16; it++) {
                const int idx = it * 32 + l;
                float4 wv = w4[idx];
                float4 v0 = x0[idx], v1 = x1[idx], v2 = x2[idx];
                a0 += wv.x*v0.x + wv.y*v0.y + wv.z*v0.z + wv.w*v0.w;
                a1 += wv.x*v1.x + wv.y*v1.y + wv.z*v1.z + wv.w*v1.w;
                a2 += wv.x*v2.x + wv.y*v2.y + wv.z*v2.z + wv.w*v2.w;
            }
            a0 = warp_sum(a0); a1 = warp_sum(a1); a2 = warp_sum(a2);
            if (l == 0) {
                const float bv = which ? bb_[rowi] : bf[rowi];
                g_u[which][0][rowi] = a0 + bv;
                g_u[which][1][rowi] = a1 + bv;
                g_u[which][2][rowi] = a2 + bv;
            }
            __syncthreads();          // protect s_chunk for next round
            c = s_chunk;
        }
    }
    grid_bar();

    // ===================== Phase C: dbc = dbc_w @ u (64 rows) ===============
    if (blk < 64) {
        const int e = blk;
        const float4* w4 = (const float4*)(Wdbc + (size_t)e * D);
        const float4* u4 = (const float4*)&g_u[0][0][0];   // 6 vecs x 512 float4

        float acc[6] = {0.f, 0.f, 0.f, 0.f, 0.f, 0.f};
        if (tid < 512) {
            float4 wv = w4[tid];
            #pragma unroll
            for (int v = 0; v < 6; v++) {
                float4 uv = u4[v * 512 + tid];
                acc[v] = wv.x*uv.x + wv.y*uv.y + wv.z*uv.z + wv.w*uv.w;
            }
        }
        #pragma unroll
        for (int v = 0; v < 6; v++) acc[v] = warp_sum(acc[v]);
        if (l == 0 && w < 16) {
            #pragma unroll
            for (int v = 0; v < 6; v++) red[w][v] = acc[v];
        }
        __syncthreads();
        if (tid < 6) {
            float s = 0.f;
            #pragma unroll
            for (int i = 0; i < 16; i++) s += red[i][tid];
            (&g_dbc[0][0][0])[tid * 64 + e] = s;
        }
    }
    grid_bar();

    // ===================== Phase D: delta / gate / residual =================
    {
        // reset stealing counters for the next launch (all grabs are done:
        // every block passed barriers 1 and 2 before any block reaches here)
        if (blk == 0 && tid == 0) { g_ctrA = 0u; g_ctrB = 0u; }

        if (tid < 2 * 3 * 64)
            (&s_dbc[0][0][0])[tid] = (&g_dbc[0][0][0])[tid];
        __syncthreads();
        if (tid < 6) {
            const int ww = tid / 3, b = tid % 3;
            float s = 0.f;
            #pragma unroll
            for (int n = 0; n < NST; n++)
                s += s_dbc[ww][b][RNK + n] * s_dbc[ww][b][RNK + NST + n];
            s_bc[ww][b] = s;
        }
        __syncthreads();

        // warp-per-d: global warp id < 2048 (blocks 0..63 active)
        const int gw = blk * NWARP + w;
        if (gw < 2048) {
            const int d = gw;
            const float wr = dtp_w[(size_t)d * RNK + l];
            float s_f[3], s_b[3];
            #pragma unroll
            for (int b = 0; b < 3; b++) {
                s_f[b] = warp_sum_all(wr * s_dbc[0][b][l]);
                s_b[b] = warp_sum_all(wr * s_dbc[1][b][l]);
            }
            if (l < 3) {
                const int b = l;
                const float tb = dtp_b[d];
                const float dpv = Dp[d];
                const float df = softplus_f(s_f[b] + tb);
                const float db = softplus_f(s_b[b] + tb);
                const float y = g_u[0][b][d] * (df * s_bc[0][b] + dpv)
                              + g_u[1][b][d] * (db * s_bc[1][b] + dpv);
                const float z = g_z1[b][d];
                const float si = z / (1.f + expf(-z));
                out[b * D + d] = y * si + x[b * D + d];
            }
        }
    }
}

// ---------------------------------------------------------------------------
extern "C" void kernel_launch(void* const* d_in, const int* in_sizes, int n_in,
                              void* d_out, int out_size) {
    const float* x    = (const float*)d_in[0];
    const float* ng   = (const float*)d_in[1]  + (size_t)LAYER * D;
    const float* nb   = (const float*)d_in[2]  + (size_t)LAYER * D;
    const float* pw   = (const float*)d_in[3]  + (size_t)LAYER * D * D;
    const float* pb   = (const float*)d_in[4]  + (size_t)LAYER * D;
    const float* fw   = (const float*)d_in[5]  + (size_t)LAYER * D * D;
    const float* fb   = (const float*)d_in[6]  + (size_t)LAYER * D;
    const float* bw   = (const float*)d_in[7]  + (size_t)LAYER * D * D;
    const float* bb   = (const float*)d_in[8]  + (size_t)LAYER * D;
    const float* dbcw = (const float*)d_in[9]  + (size_t)LAYER * (RNK + 2 * NST) * D;
    const float* dtpw = (const float*)d_in[10] + (size_t)LAYER * D * RNK;
    const float* dtpb = (const float*)d_in[11] + (size_t)LAYER * D;
    // d_in[12] = A_log : unused (seq len 1, h0 = 0 -> dA*h term vanishes)
    const float* Dp   = (const float*)d_in[13] + (size_t)LAYER * D;
    float* out = (float*)d_out;

    k_all<<<GRID, NTHR>>>(x, ng, nb, pw, pb, fw, fb, bw, bb,
                          dbcw, dtpw, dtpb, Dp, out);
}

// round 9
// speedup vs baseline: 1.2510x; 1.0741x over previous
#include <cuda_runtime.h>
#include <math.h>

#define D      2048
#define RNK    32
#define NST    16
#define LAYER  11
#define GRID   128
#define NTHR   1024
#define NWARP  32
#define NCTR   16

// Scratch (device globals; persist across graph replays)
__device__ float g_z1[3][D];
__device__ float g_u[2][3][D];               // [0]=f (fconv), [1]=bw (bconv)
__device__ float g_dbc[2][3][64];
__device__ unsigned long long g_cnt[NCTR * 32];   // barrier counters, 256B apart
__device__ unsigned long long g_nbar[GRID];       // per-block completed-barrier count

__device__ __forceinline__ float warp_sum(float v) {     // result in lane 0
    v += __shfl_down_sync(0xffffffffu, v, 16);
    v += __shfl_down_sync(0xffffffffu, v, 8);
    v += __shfl_down_sync(0xffffffffu, v, 4);
    v += __shfl_down_sync(0xffffffffu, v, 2);
    v += __shfl_down_sync(0xffffffffu, v, 1);
    return v;
}
__device__ __forceinline__ float warp_sum_all(float v) {  // result in ALL lanes
    v += __shfl_xor_sync(0xffffffffu, v, 16);
    v += __shfl_xor_sync(0xffffffffu, v, 8);
    v += __shfl_xor_sync(0xffffffffu, v, 4);
    v += __shfl_xor_sync(0xffffffffu, v, 2);
    v += __shfl_xor_sync(0xffffffffu, v, 1);
    return v;
}

// Distributed grid barrier: arrivals spread over NCTR counters (RED, no
// return) so LTS atomic serialization is 8 ops/counter instead of 128.
// Completion: counter sum == (total barriers ever) * GRID; per-block barrier
// count nbar is tracked locally (identical in every thread) and persisted in
// g_nbar[blk] (single writer) -> replay-safe, counters never reset.
__device__ __forceinline__ void grid_bar(unsigned long long& nbar,
                                         int tid, int w, int l, int blk) {
    __syncthreads();
    if (tid == 0) {
        __threadfence();                                  // publish phase writes
        atomicAdd(&g_cnt[(blk & (NCTR - 1)) * 32], 1ull); // RED (ret unused)
    }
    nbar += 1ull;
    if (w == 0) {
        const unsigned long long target = nbar * (unsigned long long)GRID;
        volatile unsigned long long* base = g_cnt;
        for (;;) {
            unsigned long long v = (l < NCTR) ? base[l * 32] : 0ull;
            v += __shfl_xor_sync(0xffffffffu, v, 1);
            v += __shfl_xor_sync(0xffffffffu, v, 2);
            v += __shfl_xor_sync(0xffffffffu, v, 4);
            v += __shfl_xor_sync(0xffffffffu, v, 8);
            v += __shfl_xor_sync(0xffffffffu, v, 16);
            if (v >= target) break;
        }
        if (l == 0) __threadfence();   // L1 invalidate before release
    }
    __syncthreads();
}

__device__ __forceinline__ float softplus_f(float v) {
    return fmaxf(v, 0.f) + log1pf(expf(-fabsf(v)));
}

// ---------------------------------------------------------------------------
// One persistent kernel (R5 phase structure + cheap barriers).
// ---------------------------------------------------------------------------
__global__ void __launch_bounds__(NTHR, 1) k_all(
        const float* __restrict__ x,
        const float* __restrict__ gam,
        const float* __restrict__ bet,
        const float* __restrict__ Wp,  const float* __restrict__ bp,
        const float* __restrict__ Wf,  const float* __restrict__ bf,
        const float* __restrict__ Wb,  const float* __restrict__ bb_,
        const float* __restrict__ Wdbc,
        const float* __restrict__ dtp_w,
        const float* __restrict__ dtp_b,
        const float* __restrict__ Dp,
        float* __restrict__ out) {
    __shared__ float s_in[3][D];          // 24 KB (xn, then z1)
    __shared__ float red[NWARP][6];
    __shared__ float s_part[NWARP][3];
    __shared__ float mu_s[3], inv_s[3];
    __shared__ float s_dbc[2][3][64];
    __shared__ float s_bc[2][3];

    const int tid = threadIdx.x;
    const int w   = tid >> 5;
    const int l   = tid & 31;
    const int blk = blockIdx.x;

    unsigned long long nbar = g_nbar[blk];   // same value in all threads

    // ===================== Phase A: layernorm + proj ========================
    {
        float sm[3] = {0.f, 0.f, 0.f}, sq[3] = {0.f, 0.f, 0.f};
        #pragma unroll
        for (int rep = 0; rep < 2; rep++) {
            const int i = rep * NTHR + tid;
            #pragma unroll
            for (int b = 0; b < 3; b++) {
                float v = x[b * D + i];
                s_in[b][i] = v;
                sm[b] += v;
                sq[b] += v * v;
            }
        }
        #pragma unroll
        for (int b = 0; b < 3; b++) { sm[b] = warp_sum(sm[b]); sq[b] = warp_sum(sq[b]); }
        if (l == 0) {
            #pragma unroll
            for (int b = 0; b < 3; b++) { red[w][b] = sm[b]; red[w][3 + b] = sq[b]; }
        }
        __syncthreads();
        if (tid < 3) {
            float S = 0.f, Q = 0.f;
            #pragma unroll
            for (int i = 0; i < NWARP; i++) { S += red[i][tid]; Q += red[i][3 + tid]; }
            float mu = S * (1.f / D);
            float var = Q * (1.f / D) - mu * mu;
            mu_s[tid] = mu;
            inv_s[tid] = rsqrtf(var + 1e-5f);
        }
        __syncthreads();
        const float m0 = mu_s[0], m1 = mu_s[1], m2 = mu_s[2];
        const float i0 = inv_s[0], i1 = inv_s[1], i2 = inv_s[2];
        #pragma unroll
        for (int rep = 0; rep < 2; rep++) {
            const int i = rep * NTHR + tid;
            const float g = gam[i], be = bet[i];
            s_in[0][i] = (s_in[0][i] - m0) * i0 * g + be;
            s_in[1][i] = (s_in[1][i] - m1) * i1 * g + be;
            s_in[2][i] = (s_in[2][i] - m2) * i2 * g + be;
        }
        __syncthreads();

        // half-row per warp: 32 warps -> 16 rows/block -> 2048 rows
        const int rw   = w >> 1;
        const int half = w & 1;
        const int row  = blk * 16 + rw;
        const float4* wp4 = (const float4*)(Wp + (size_t)row * D) + half * 256;
        const float4* x0 = (const float4*)s_in[0] + half * 256;
        const float4* x1 = (const float4*)s_in[1] + half * 256;
        const float4* x2 = (const float4*)s_in[2] + half * 256;
        float a0 = 0.f, a1 = 0.f, a2 = 0.f;
        #pragma unroll
        for (int it = 0; it < 8; it++) {
            const int idx = it * 32 + l;
            float4 wv = wp4[idx];
            float4 v0 = x0[idx], v1 = x1[idx], v2 = x2[idx];
            a0 += wv.x*v0.x + wv.y*v0.y + wv.z*v0.z + wv.w*v0.w;
            a1 += wv.x*v1.x + wv.y*v1.y + wv.z*v1.z + wv.w*v1.w;
            a2 += wv.x*v2.x + wv.y*v2.y + wv.z*v2.z + wv.w*v2.w;
        }
        a0 = warp_sum(a0); a1 = warp_sum(a1); a2 = warp_sum(a2);
        if (l == 0) { s_part[w][0] = a0; s_part[w][1] = a1; s_part[w][2] = a2; }
        __syncthreads();
        if (tid < 48) {   // 16 rows x 3 batches
            const int rr = tid / 3, b = tid % 3;
            const int row_g = blk * 16 + rr;
            g_z1[b][row_g] = s_part[2 * rr][b] + s_part[2 * rr + 1][b] + bp[row_g];
        }
    }
    grid_bar(nbar, tid, w, l, blk);

    // ===================== Phase B: f/b conv matvecs ========================
    {
        #pragma unroll
        for (int rep = 0; rep < 6; rep++)
            (&s_in[0][0])[rep * NTHR + tid] = (&g_z1[0][0])[rep * NTHR + tid];
        __syncthreads();

        // 1 full row per warp: 128 blocks x 32 warps = 4096 rows
        const int which = (blk >= 64) ? 1 : 0;
        const int row = (blk & 63) * 32 + w;
        const float* W = which ? Wb : Wf;
        const float* bias = which ? bb_ : bf;

        const float4* w4 = (const float4*)(W + (size_t)row * D);
        const float4* x0 = (const float4*)s_in[0];
        const float4* x1 = (const float4*)s_in[1];
        const float4* x2 = (const float4*)s_in[2];
        float a0 = 0.f, a1 = 0.f, a2 = 0.f;
        #pragma unroll
        for (int it = 0; it < 16; it++) {
            const int idx = it * 32 + l;
            float4 wv = w4[idx];
            float4 v0 = x0[idx], v1 = x1[idx], v2 = x2[idx];
            a0 += wv.x*v0.x + wv.y*v0.y + wv.z*v0.z + wv.w*v0.w;
            a1 += wv.x*v1.x + wv.y*v1.y + wv.z*v1.z + wv.w*v1.w;
            a2 += wv.x*v2.x + wv.y*v2.y + wv.z*v2.z + wv.w*v2.w;
        }
        a0 = warp_sum(a0); a1 = warp_sum(a1); a2 = warp_sum(a2);
        if (l == 0) {
            const float bv = bias[row];
            g_u[which][0][row] = a0 + bv;
            g_u[which][1][row] = a1 + bv;
            g_u[which][2][row] = a2 + bv;
        }
    }
    grid_bar(nbar, tid, w, l, blk);

    // ===================== Phase C: dbc = dbc_w @ u (64 rows) ===============
    if (blk < 64) {
        const int e = blk;
        const float4* w4 = (const float4*)(Wdbc + (size_t)e * D);
        const float4* u4 = (const float4*)&g_u[0][0][0];   // 6 vecs x 512 float4

        const int grp = tid >> 9;          // 0: vecs 0-2, 1: vecs 3-5
        const int idx = tid & 511;
        float4 wv = w4[idx];
        float acc[3];
        #pragma unroll
        for (int v = 0; v < 3; v++) {
            float4 uv = u4[(grp * 3 + v) * 512 + idx];
            acc[v] = wv.x*uv.x + wv.y*uv.y + wv.z*uv.z + wv.w*uv.w;
        }
        #pragma unroll
        for (int v = 0; v < 3; v++) acc[v] = warp_sum(acc[v]);
        if (l == 0) {
            #pragma unroll
            for (int v = 0; v < 3; v++) red[w][v] = acc[v];
        }
        __syncthreads();
        if (tid < 6) {
            const int base = (tid / 3) * 16;   // warps 0-15 grp0, 16-31 grp1
            float s = 0.f;
            #pragma unroll
            for (int i = 0; i < 16; i++) s += red[base + i][tid % 3];
            (&g_dbc[0][0][0])[tid * 64 + e] = s;
        }
    }
    grid_bar(nbar, tid, w, l, blk);

    // ===================== Phase D: delta / gate / residual =================
    {
        if (tid < 2 * 3 * 64)
            (&s_dbc[0][0][0])[tid] = (&g_dbc[0][0][0])[tid];
        __syncthreads();
        if (tid < 6) {
            const int ww = tid / 3, b = tid % 3;
            float s = 0.f;
            #pragma unroll
            for (int n = 0; n < NST; n++)
                s += s_dbc[ww][b][RNK + n] * s_dbc[ww][b][RNK + NST + n];
            s_bc[ww][b] = s;
        }
        __syncthreads();

        // warp-per-d: warps 0..15 of each block -> 2048 d's
        if (w < 16) {
            const int d = blk * 16 + w;
            const float wr = dtp_w[(size_t)d * RNK + l];
            float s_f[3], s_b[3];
            #pragma unroll
            for (int b = 0; b < 3; b++) {
                s_f[b] = warp_sum_all(wr * s_dbc[0][b][l]);
                s_b[b] = warp_sum_all(wr * s_dbc[1][b][l]);
            }
            if (l < 3) {
                const int b = l;
                const float tb = dtp_b[d];
                const float dpv = Dp[d];
                const float df = softplus_f(s_f[b] + tb);
                const float db = softplus_f(s_b[b] + tb);
                const float y = g_u[0][b][d] * (df * s_bc[0][b] + dpv)
                              + g_u[1][b][d] * (db * s_bc[1][b] + dpv);
                const float z = g_z1[b][d];
                const float si = z / (1.f + expf(-z));
                out[b * D + d] = y * si + x[b * D + d];
            }
        }
        // persist this block's barrier count for the next launch
        if (tid == 0) g_nbar[blk] = nbar;
    }
}

// ---------------------------------------------------------------------------
extern "C" void kernel_launch(void* const* d_in, const int* in_sizes, int n_in,
                              void* d_out, int out_size) {
    const float* x    = (const float*)d_in[0];
    const float* ng   = (const float*)d_in[1]  + (size_t)LAYER * D;
    const float* nb   = (const float*)d_in[2]  + (size_t)LAYER * D;
    const float* pw   = (const float*)d_in[3]  + (size_t)LAYER * D * D;
    const float* pb   = (const float*)d_in[4]  + (size_t)LAYER * D;
    const float* fw   = (const float*)d_in[5]  + (size_t)LAYER * D * D;
    const float* fb   = (const float*)d_in[6]  + (size_t)LAYER * D;
    const float* bw   = (const float*)d_in[7]  + (size_t)LAYER * D * D;
    const float* bb   = (const float*)d_in[8]  + (size_t)LAYER * D;
    const float* dbcw = (const float*)d_in[9]  + (size_t)LAYER * (RNK + 2 * NST) * D;
    const float* dtpw = (const float*)d_in[10] + (size_t)LAYER * D * RNK;
    const float* dtpb = (const float*)d_in[11] + (size_t)LAYER * D;
    // d_in[12] = A_log : unused (seq len 1, h0 = 0 -> dA*h term vanishes)
    const float* Dp   = (const float*)d_in[13] + (size_t)LAYER * D;
    float* out = (float*)d_out;

    k_all<<<GRID, NTHR>>>(x, ng, nb, pw, pb, fw, fb, bw, bb,
                          dbcw, dtpw, dtpb, Dp, out);
}